// round 1
// baseline (speedup 1.0000x reference)
#include <cuda_runtime.h>
#include <math.h>

#define C 21
#define FG 20
#define TOPK 512
#define CAND_STRIDE 262144
#define SORTCAP 8192
#define DETS 100
#define SCORE_TH 0.05f
#define NMS_TH 0.5f
#define BBOX_CLIPV 4.135166556742356f

// ---------------- scratch (static device allocations; no runtime alloc) ----
__device__ unsigned int       g_hist[FG * 65536];          // 5.2 MB
__device__ int                g_cnt[FG];
__device__ int                g_cut[FG];
__device__ unsigned long long g_cand[FG * CAND_STRIDE];    // 42 MB
__device__ float              g_vals[FG * TOPK];
__device__ int                g_keep[FG * TOPK];
__device__ float              g_obox[FG * TOPK * 7];

__device__ __forceinline__ unsigned long long umax64(unsigned long long a,
                                                     unsigned long long b) {
    return a > b ? a : b;
}

// ---------------- K0: zero hist + counters ---------------------------------
__global__ void zero_kernel() {
    int i = blockIdx.x * blockDim.x + threadIdx.x;
    const int total = FG * 65536;
    for (; i < total; i += gridDim.x * blockDim.x) g_hist[i] = 0u;
    if (blockIdx.x == 0 && threadIdx.x < FG) g_cnt[threadIdx.x] = 0;
}

// ---------------- K1: softmax + candidate compaction + histogram -----------
__global__ void score_kernel(const float* __restrict__ logits, int N) {
    __shared__ float sl[256 * C];
    int base = blockIdx.x * 256;
    int nrows = min(256, N - base);
    if (nrows <= 0) return;
    int lim = nrows * C;
    for (int i = threadIdx.x; i < lim; i += 256) sl[i] = logits[(size_t)base * C + i];
    __syncthreads();
    int row = base + threadIdx.x;
    if (threadIdx.x >= nrows) return;

    float e[C];
    float s = 0.f;
#pragma unroll
    for (int j = 0; j < C; j++) {
        e[j] = expf(sl[threadIdx.x * C + j]);
        s += e[j];
    }
    float inv = 1.0f / s;
#pragma unroll
    for (int c = 1; c < C; c++) {
        float p = e[c] * inv;
        if (p > SCORE_TH) {
            int cl = c - 1;
            unsigned int bits = __float_as_uint(p);
            atomicAdd(&g_hist[(cl << 16) | (bits >> 16)], 1u);
            int pos = atomicAdd(&g_cnt[cl], 1);
            g_cand[cl * CAND_STRIDE + pos] =
                ((unsigned long long)bits << 32) |
                (unsigned long long)(0xFFFFFFFFu - (unsigned int)row);
        }
    }
}

// ---------------- K2: per-class cutoff bin for rank-512 ---------------------
__global__ void cutoff_kernel() {
    int c = blockIdx.x;
    __shared__ unsigned int chunk[256];
    const unsigned int* h = &g_hist[c << 16];
    int t = threadIdx.x;
    unsigned int sum = 0;
    for (int b = 0; b < 256; b++) sum += h[t * 256 + b];
    chunk[t] = sum;
    __syncthreads();
    if (t == 0) {
        unsigned int cum = 0;
        int B = 0;
        for (int ck = 255; ck >= 0; ck--) {
            if (cum + chunk[ck] >= TOPK) {
                for (int b = ck * 256 + 255; b >= ck * 256; b--) {
                    cum += h[b];
                    if (cum >= TOPK) { B = b; break; }
                }
                break;
            }
            cum += chunk[ck];
        }
        g_cut[c] = B;  // 0 if total < 512 (keep everything)
    }
}

// ---------------- K3: per-class filter+sort+decode+NMS ----------------------
// dynamic smem layout (65536 B):
//   [0      .. 65536) u64 skey[8192]   (sort buffer; top-512 survive at front)
//   [4096   .. 18432) 7 x float[512]   (derived box geometry, reuses skey[512..])
//   [18432  .. 51200) u32 ov[16*512]   (IoU>0.5 bit-matrix, transposed)
__global__ void classproc_kernel(const float* __restrict__ breg,
                                 const float* __restrict__ props) {
    extern __shared__ unsigned char smraw[];
    unsigned long long* skey = (unsigned long long*)smraw;
    float* dv  = (float*)(smraw + 4096);
    float* xl  = dv;           float* xh = dv + 512;
    float* yl  = dv + 1024;    float* yh = dv + 1536;
    float* zl  = dv + 2048;    float* zh = dv + 2560;
    float* vol = dv + 3072;
    unsigned int* ov = (unsigned int*)(smraw + 18432);

    __shared__ int scount;
    __shared__ unsigned int keepw[16];
    __shared__ unsigned char validf[512];

    int c   = blockIdx.x;
    int tid = threadIdx.x;
    int cnt = g_cnt[c];
    unsigned int B = (unsigned int)g_cut[c];
    if (tid == 0) scount = 0;
    __syncthreads();

    // filter candidates with bin >= cutoff into smem
    const unsigned long long* cand = &g_cand[c * CAND_STRIDE];
    for (int i = tid; i < cnt; i += 512) {
        unsigned long long k = cand[i];
        if ((unsigned int)(k >> 48) >= B) {
            int p = atomicAdd(&scount, 1);
            if (p < SORTCAP) skey[p] = k;
        }
    }
    __syncthreads();
    int m = min(scount, SORTCAP);
    int n = 512;
    while (n < m) n <<= 1;
    for (int i = m + tid; i < n; i += 512) skey[i] = 0ULL;
    __syncthreads();

    // bitonic sort descending (unique keys: score bits + inverted row index)
    for (int k = 2; k <= n; k <<= 1) {
        for (int j = k >> 1; j > 0; j >>= 1) {
            for (int i = tid; i < n; i += 512) {
                int ixj = i ^ j;
                if (ixj > i) {
                    unsigned long long a = skey[i], b = skey[ixj];
                    bool desc = ((i & k) == 0);
                    if (desc ? (a < b) : (a > b)) { skey[i] = b; skey[ixj] = a; }
                }
            }
            __syncthreads();
        }
    }

    // decode top-512
    unsigned long long k0 = skey[tid];
    float score = __uint_as_float((unsigned int)(k0 >> 32));
    int   row   = (int)(0xFFFFFFFFu - (unsigned int)(k0 & 0xFFFFFFFFu));
    int   valid = score > SCORE_TH;
    if (!valid) row = 0;  // pad entries decode a dummy box; never kept
    validf[tid] = (unsigned char)valid;

    const float* pr = props + (size_t)row * 7;
    const float* d  = breg + (size_t)row * (C * 7) + (c + 1) * 7;
    float px = pr[0], py = pr[1], pzb = pr[2];
    float psx = pr[3], psy = pr[4], psz = pr[5], pry = pr[6];
    float pcz = pzb + psz * 0.5f;
    float cx = px + (d[0] / 10.0f) * psx;
    float cy = py + (d[1] / 10.0f) * psy;
    float cz = pcz + (d[2] / 10.0f) * psz;
    float sx = psx * expf(fminf(d[3] / 5.0f, BBOX_CLIPV));
    float sy = psy * expf(fminf(d[4] / 5.0f, BBOX_CLIPV));
    float sz = psz * expf(fminf(d[5] / 5.0f, BBOX_CLIPV));
    float ry = pry + d[6];
    float zb = cz - sz * 0.5f;

    float* ob = &g_obox[(c * TOPK + tid) * 7];
    ob[0] = cx; ob[1] = cy; ob[2] = zb; ob[3] = sx;
    ob[4] = sy; ob[5] = sz; ob[6] = ry;
    g_vals[c * TOPK + tid] = score;

    float bxl = cx - sx * 0.5f, bxh = cx + sx * 0.5f;
    float byl = cy - sy * 0.5f, byh = cy + sy * 0.5f;
    float bzl = zb,             bzh = zb + sz;
    float bvol = sx * sy * sz;
    xl[tid] = bxl; xh[tid] = bxh; yl[tid] = byl; yh[tid] = byh;
    zl[tid] = bzl; zh[tid] = bzh; vol[tid] = bvol;
    __syncthreads();

    // IoU bit-matrix (symmetric; fp order matches reference exactly)
    {
        unsigned int word = 0;
        for (int j = 0; j < 512; j++) {
            float ox = fmaxf(fminf(bxh, xh[j]) - fmaxf(bxl, xl[j]), 0.f);
            float oy = fmaxf(fminf(byh, yh[j]) - fmaxf(byl, yl[j]), 0.f);
            float oz = fmaxf(fminf(bzh, zh[j]) - fmaxf(bzl, zl[j]), 0.f);
            float inter = ox * oy * oz;
            float iou = inter / (bvol + vol[j] - inter + 1e-7f);
            word |= (iou > NMS_TH ? 1u : 0u) << (j & 31);
            if ((j & 31) == 31) { ov[(j >> 5) * 512 + tid] = word; word = 0; }
        }
    }
    __syncthreads();

    // greedy sequential NMS over bitset by warp 0 (16 active words)
    if (tid < 32) {
        int lane = tid;
        if (lane < 16) keepw[lane] = 0u;
        __syncwarp();
        for (int i = 0; i < 512; i++) {
            unsigned int x = (lane < 16) ? (ov[lane * 512 + i] & keepw[lane]) : 0u;
            int sup = __any_sync(0xFFFFFFFFu, x != 0u);
            int kk  = validf[i] && !sup;
            if (lane == (i >> 5)) keepw[lane] |= ((unsigned int)kk) << (i & 31);
            __syncwarp();
        }
    }
    __syncthreads();
    g_keep[c * TOPK + tid] = (keepw[tid >> 5] >> (tid & 31)) & 1;
}

// ---------------- K4: global top-100 + output -------------------------------
__global__ void final_kernel(float* __restrict__ out) {
    extern __shared__ unsigned long long keys[];
    __shared__ unsigned long long red[32];
    const int TOT = FG * TOPK;
    int tid = threadIdx.x;

    for (int i = tid; i < TOT; i += 1024) {
        float f = g_keep[i] ? g_vals[i] : -1e9f;
        unsigned int u = __float_as_uint(f);
        u = (u & 0x80000000u) ? ~u : (u | 0x80000000u);  // monotone float->uint
        keys[i] = ((unsigned long long)u << 32) |
                  (unsigned long long)(0xFFFFFFFFu - (unsigned int)i);
    }
    __syncthreads();

    for (int r = 0; r < DETS; r++) {
        unsigned long long best = 0;
        for (int i = tid; i < TOT; i += 1024) best = umax64(best, keys[i]);
#pragma unroll
        for (int o = 16; o > 0; o >>= 1)
            best = umax64(best, __shfl_down_sync(0xFFFFFFFFu, best, o));
        if ((tid & 31) == 0) red[tid >> 5] = best;
        __syncthreads();
        if (tid < 32) {
            unsigned long long b = red[tid];
#pragma unroll
            for (int o = 16; o > 0; o >>= 1)
                b = umax64(b, __shfl_down_sync(0xFFFFFFFFu, b, o));
            if (tid == 0) red[0] = b;
        }
        __syncthreads();
        unsigned long long win = red[0];
        for (int i = tid; i < TOT; i += 1024) {
            if (keys[i] == win) {
                keys[i] = 0;
                int idx = (int)(0xFFFFFFFFu - (unsigned int)(win & 0xFFFFFFFFu));
                float* o = out + r * 9;
                const float* b = &g_obox[idx * 7];
#pragma unroll
                for (int k = 0; k < 7; k++) o[k] = b[k];
                o[7] = g_keep[idx] ? g_vals[idx] : -1e9f;
                o[8] = (float)((idx >> 9) + 1);
            }
        }
        __syncthreads();
    }
}

// ---------------- launcher --------------------------------------------------
extern "C" void kernel_launch(void* const* d_in, const int* in_sizes, int n_in,
                              void* d_out, int out_size) {
    const float* logits = (const float*)d_in[0];   // (N, 21)
    const float* breg   = (const float*)d_in[1];   // (N, 147)
    const float* props  = (const float*)d_in[2];   // (N, 7)
    int N = in_sizes[2] / 7;

    cudaFuncSetAttribute(classproc_kernel,
                         cudaFuncAttributeMaxDynamicSharedMemorySize, 65536);
    cudaFuncSetAttribute(final_kernel,
                         cudaFuncAttributeMaxDynamicSharedMemorySize,
                         FG * TOPK * 8);

    zero_kernel<<<256, 256>>>();
    score_kernel<<<(N + 255) / 256, 256>>>(logits, N);
    cutoff_kernel<<<FG, 256>>>();
    classproc_kernel<<<FG, 512, 65536>>>(breg, props);
    final_kernel<<<1, 1024, FG * TOPK * 8>>>((float*)d_out);
}

// round 2
// speedup vs baseline: 2.6890x; 2.6890x over previous
#include <cuda_runtime.h>
#include <math.h>

#define C 21
#define FG 20
#define TOPK 512
#define CAND_STRIDE 262144
#define SORTCAP 8192
#define DETS 100
#define SCORE_TH 0.05f
#define NMS_TH 0.5f
#define BBOX_CLIPV 4.135166556742356f

// ---------------- static device scratch ------------------------------------
__device__ unsigned int       g_hist[FG * 65536];
__device__ int                g_cnt[FG];
__device__ int                g_cut[FG];
__device__ unsigned long long g_cand[FG * CAND_STRIDE];
__device__ float              g_vals[FG * TOPK];
__device__ int                g_keep[FG * TOPK];
__device__ float              g_obox[FG * TOPK * 7];
__device__ float              g_geo[FG * 7 * TOPK];     // SoA: xl,xh,yl,yh,zl,zh,vol
__device__ unsigned int       g_ov[FG * 16 * TOPK];     // IoU>0.5 bit matrix (col-major words)
__device__ unsigned long long g_top[FG * 128];          // first <=128 kept keys per class
__device__ int                g_topn[FG];
__device__ unsigned long long g_fill[128];              // class-0 non-kept fillers
__device__ int                g_filln;

// ---------------- K0: zero hist + counters ---------------------------------
__global__ void zero_kernel() {
    int i = blockIdx.x * blockDim.x + threadIdx.x;
    const int total = FG * 65536;
    for (; i < total; i += gridDim.x * blockDim.x) g_hist[i] = 0u;
    if (blockIdx.x == 0 && threadIdx.x < FG) g_cnt[threadIdx.x] = 0;
}

// ---------------- K1: softmax + compaction (block-aggregated atomics) -------
__global__ void score_kernel(const float* __restrict__ logits, int N) {
    __shared__ float sl[256 * C];
    __shared__ int scnt[FG], sbase[FG], swr[FG];
    int base = blockIdx.x * 256;
    int tid = threadIdx.x;
    if (tid < FG) { scnt[tid] = 0; swr[tid] = 0; }
    int nrows = min(256, N - base);
    if (nrows <= 0) return;
    int lim = nrows * C;
    for (int i = tid; i < lim; i += 256) sl[i] = logits[(size_t)base * C + i];
    __syncthreads();

    float e[C];
    float inv = 0.f;
    int row = base + tid;
    bool active = tid < nrows;
    if (active) {
        float m = sl[tid * C];
#pragma unroll
        for (int j = 1; j < C; j++) m = fmaxf(m, sl[tid * C + j]);
        float s = 0.f;
#pragma unroll
        for (int j = 0; j < C; j++) { e[j] = __expf(sl[tid * C + j] - m); s += e[j]; }
        inv = 1.0f / s;
#pragma unroll
        for (int c = 1; c < C; c++)
            if (e[c] * inv > SCORE_TH) atomicAdd(&scnt[c - 1], 1);
    }
    __syncthreads();
    if (tid < FG) sbase[tid] = atomicAdd(&g_cnt[tid], scnt[tid]);
    __syncthreads();
    if (active) {
#pragma unroll
        for (int c = 1; c < C; c++) {
            float p = e[c] * inv;
            if (p > SCORE_TH) {
                int cl = c - 1;
                unsigned int bits = __float_as_uint(p);
                atomicAdd(&g_hist[(cl << 16) | (bits >> 16)], 1u);
                int pos = sbase[cl] + atomicAdd(&swr[cl], 1);
                g_cand[cl * CAND_STRIDE + pos] =
                    ((unsigned long long)bits << 32) |
                    (unsigned long long)(0xFFFFFFFFu - (unsigned int)row);
            }
        }
    }
}

// ---------------- K2: per-class cutoff bin for rank-512 ---------------------
__global__ void cutoff_kernel() {
    int c = blockIdx.x;
    __shared__ unsigned int chunk[256];
    const unsigned int* h = &g_hist[c << 16];
    int t = threadIdx.x;
    unsigned int sum = 0;
    for (int b = 0; b < 256; b++) sum += h[t * 256 + b];
    chunk[t] = sum;
    __syncthreads();
    if (t == 0) {
        unsigned int cum = 0;
        int B = 0;
        for (int ck = 255; ck >= 0; ck--) {
            if (cum + chunk[ck] >= TOPK) {
                for (int b = ck * 256 + 255; b >= ck * 256; b--) {
                    cum += h[b];
                    if (cum >= TOPK) { B = b; break; }
                }
                break;
            }
            cum += chunk[ck];
        }
        g_cut[c] = B;
    }
}

// ---------------- K3a: filter + bitonic sort + decode + geometry ------------
__global__ void select_kernel(const float* __restrict__ breg,
                              const float* __restrict__ props) {
    extern __shared__ unsigned long long skey[];  // 8192 u64
    __shared__ int scount;
    int c = blockIdx.x, tid = threadIdx.x;
    int cnt = g_cnt[c];
    unsigned int B = (unsigned int)g_cut[c];
    if (tid == 0) scount = 0;
    __syncthreads();

    const unsigned long long* cand = &g_cand[c * CAND_STRIDE];
    for (int i = tid; i < cnt; i += 512) {
        unsigned long long k = cand[i];
        if ((unsigned int)(k >> 48) >= B) {
            int p = atomicAdd(&scount, 1);
            if (p < SORTCAP) skey[p] = k;
        }
    }
    __syncthreads();
    int m = min(scount, SORTCAP);
    int n = 512;
    while (n < m) n <<= 1;
    for (int i = m + tid; i < n; i += 512) skey[i] = 0ULL;
    __syncthreads();

    for (int k = 2; k <= n; k <<= 1) {
        for (int j = k >> 1; j > 0; j >>= 1) {
            for (int i = tid; i < n; i += 512) {
                int ixj = i ^ j;
                if (ixj > i) {
                    unsigned long long a = skey[i], b = skey[ixj];
                    bool desc = ((i & k) == 0);
                    if (desc ? (a < b) : (a > b)) { skey[i] = b; skey[ixj] = a; }
                }
            }
            __syncthreads();
        }
    }

    unsigned long long k0 = skey[tid];
    float score = __uint_as_float((unsigned int)(k0 >> 32));
    int row = (int)(0xFFFFFFFFu - (unsigned int)(k0 & 0xFFFFFFFFu));
    if (!(score > SCORE_TH)) row = 0;

    const float* pr = props + (size_t)row * 7;
    const float* d = breg + (size_t)row * (C * 7) + (c + 1) * 7;
    float px = pr[0], py = pr[1], pzb = pr[2];
    float psx = pr[3], psy = pr[4], psz = pr[5], pry = pr[6];
    float pcz = pzb + psz * 0.5f;
    float cx = px + (d[0] / 10.0f) * psx;
    float cy = py + (d[1] / 10.0f) * psy;
    float cz = pcz + (d[2] / 10.0f) * psz;
    float sx = psx * expf(fminf(d[3] / 5.0f, BBOX_CLIPV));
    float sy = psy * expf(fminf(d[4] / 5.0f, BBOX_CLIPV));
    float sz = psz * expf(fminf(d[5] / 5.0f, BBOX_CLIPV));
    float ry = pry + d[6];
    float zb = cz - sz * 0.5f;

    float* ob = &g_obox[(c * TOPK + tid) * 7];
    ob[0] = cx; ob[1] = cy; ob[2] = zb; ob[3] = sx;
    ob[4] = sy; ob[5] = sz; ob[6] = ry;
    g_vals[c * TOPK + tid] = score;

    float* gg = &g_geo[c * 7 * TOPK];
    gg[0 * TOPK + tid] = cx - sx * 0.5f;
    gg[1 * TOPK + tid] = cx + sx * 0.5f;
    gg[2 * TOPK + tid] = cy - sy * 0.5f;
    gg[3 * TOPK + tid] = cy + sy * 0.5f;
    gg[4 * TOPK + tid] = zb;
    gg[5 * TOPK + tid] = zb + sz;
    gg[6 * TOPK + tid] = sx * sy * sz;
}

// ---------------- K3b: IoU bit-matrix, division-free, full chip -------------
__global__ void iou_kernel() {
    __shared__ float sj[7][64];
    int c = blockIdx.y, g = blockIdx.x, tid = threadIdx.x;
    int jbase = g * 64;
    const float* gg = &g_geo[c * 7 * TOPK];
    for (int t = tid; t < 7 * 64; t += 512) {
        int k = t >> 6, jj = t & 63;
        sj[k][jj] = gg[k * TOPK + jbase + jj];
    }
    float xl = gg[0 * TOPK + tid], xh = gg[1 * TOPK + tid];
    float yl = gg[2 * TOPK + tid], yh = gg[3 * TOPK + tid];
    float zl = gg[4 * TOPK + tid], zh = gg[5 * TOPK + tid];
    float vo = gg[6 * TOPK + tid];
    __syncthreads();

#pragma unroll
    for (int w = 0; w < 2; w++) {
        unsigned int word = 0;
#pragma unroll
        for (int b = 0; b < 32; b++) {
            int j = w * 32 + b;
            float ox = fmaxf(fminf(xh, sj[1][j]) - fmaxf(xl, sj[0][j]), 0.f);
            float oy = fmaxf(fminf(yh, sj[3][j]) - fmaxf(yl, sj[2][j]), 0.f);
            float oz = fmaxf(fminf(zh, sj[5][j]) - fmaxf(zl, sj[4][j]), 0.f);
            float inter = ox * oy * oz;
            float denom = vo + sj[6][j] - inter + 1e-7f;
            word |= (inter > NMS_TH * denom ? 1u : 0u) << b;
        }
        g_ov[c * (16 * TOPK) + (g * 2 + w) * TOPK + tid] = word;
    }
}

// ---------------- K3c: serial NMS (register masks) + kept compaction --------
__global__ void nms_kernel() {
    __shared__ unsigned int sov[16 * TOPK];
    __shared__ unsigned int vmask[16];
    __shared__ unsigned int keepw[16];
    int c = blockIdx.x, tid = threadIdx.x;
    for (int i = tid; i < 16 * TOPK; i += 512) sov[i] = g_ov[c * (16 * TOPK) + i];
    int valid = g_vals[c * TOPK + tid] > SCORE_TH;
    unsigned int bal = __ballot_sync(0xFFFFFFFFu, valid);
    if ((tid & 31) == 0) vmask[tid >> 5] = bal;
    __syncthreads();

    if (tid < 32) {
        int lane = tid;
        unsigned int kw = 0;
        unsigned int vw = lane < 16 ? vmask[lane] : 0u;
        unsigned int cur = lane < 16 ? sov[lane * TOPK] : 0u;
        for (int i = 0; i < TOPK; i++) {
            unsigned int nxt = (lane < 16 && i < TOPK - 1) ? sov[lane * TOPK + i + 1] : 0u;
            int sup = __any_sync(0xFFFFFFFFu, (cur & kw) != 0u);
            if (lane == (i >> 5)) {
                unsigned int kk = ((vw >> (i & 31)) & 1u) & (unsigned int)(!sup);
                kw |= kk << (i & 31);
            }
            cur = nxt;
        }
        if (lane < 16) keepw[lane] = kw;
    }
    __syncthreads();

    int w = tid >> 5, b = tid & 31;
    int keep = (keepw[w] >> b) & 1;
    int flat = c * TOPK + tid;
    g_keep[flat] = keep;
    int rank = 0;
    for (int ww = 0; ww < w; ww++) rank += __popc(keepw[ww]);
    rank += __popc(keepw[w] & ((1u << b) - 1u));

    if (keep && rank < 128) {
        unsigned int ms = __float_as_uint(g_vals[flat]) | 0x80000000u;  // score > 0
        g_top[c * 128 + rank] =
            ((unsigned long long)ms << 32) |
            (unsigned long long)(0xFFFFFFFFu - (unsigned int)flat);
    }
    if (tid == TOPK - 1) g_topn[c] = min(rank + keep, 128);
    if (c == 0) {
        int nrank = tid - rank;  // non-kept rank in flat order
        if (!keep && nrank < 128) {
            unsigned int ms = ~__float_as_uint(-1e9f);  // monotone map, negative
            g_fill[nrank] =
                ((unsigned long long)ms << 32) |
                (unsigned long long)(0xFFFFFFFFu - (unsigned int)flat);
        }
        if (tid == TOPK - 1) g_filln = min(TOPK - (rank + keep), 128);
    }
}

// ---------------- K4: global top-100 via 4096-key bitonic sort --------------
__global__ void final_kernel(float* __restrict__ out) {
    __shared__ unsigned long long keys[4096];
    int tid = threadIdx.x;  // 1024
    const int SLOTS = FG * 128;
    for (int i = tid; i < 4096; i += 1024) {
        unsigned long long k = 0;
        if (i < SLOTS) {
            int c = i >> 7, r = i & 127;
            if (r < g_topn[c]) k = g_top[i];
        } else if (i < SLOTS + 128) {
            int r = i - SLOTS;
            if (r < g_filln) k = g_fill[r];
        }
        keys[i] = k;
    }
    __syncthreads();
    for (int k = 2; k <= 4096; k <<= 1) {
        for (int j = k >> 1; j > 0; j >>= 1) {
            for (int i = tid; i < 4096; i += 1024) {
                int ixj = i ^ j;
                if (ixj > i) {
                    unsigned long long a = keys[i], bb = keys[ixj];
                    bool desc = ((i & k) == 0);
                    if (desc ? (a < bb) : (a > bb)) { keys[i] = bb; keys[ixj] = a; }
                }
            }
            __syncthreads();
        }
    }
    if (tid < DETS) {
        unsigned long long k = keys[tid];
        int flat = (int)(0xFFFFFFFFu - (unsigned int)(k & 0xFFFFFFFFu));
        float* o = out + tid * 9;
        const float* bx = &g_obox[flat * 7];
#pragma unroll
        for (int q = 0; q < 7; q++) o[q] = bx[q];
        o[7] = g_keep[flat] ? g_vals[flat] : -1e9f;
        o[8] = (float)((flat >> 9) + 1);
    }
}

// ---------------- launcher --------------------------------------------------
extern "C" void kernel_launch(void* const* d_in, const int* in_sizes, int n_in,
                              void* d_out, int out_size) {
    const float* logits = (const float*)d_in[0];
    const float* breg   = (const float*)d_in[1];
    const float* props  = (const float*)d_in[2];
    int N = in_sizes[2] / 7;

    cudaFuncSetAttribute(select_kernel,
                         cudaFuncAttributeMaxDynamicSharedMemorySize, 65536);

    zero_kernel<<<256, 256>>>();
    score_kernel<<<(N + 255) / 256, 256>>>(logits, N);
    cutoff_kernel<<<FG, 256>>>();
    select_kernel<<<FG, 512, 65536>>>(breg, props);
    iou_kernel<<<dim3(8, FG), 512>>>();
    nms_kernel<<<FG, 512>>>();
    final_kernel<<<1, 1024>>>((float*)d_out);
}